// round 1
// baseline (speedup 1.0000x reference)
#include <cuda_runtime.h>

#ifndef PI_F
#define PI_F 3.14159265358979323846f
#endif

// ---------------- dims ----------------
// x: (8, 4096, 512)   rows = 32768
// u: rows x 1024, v: rows x 512
// DPB: 8192 circulant rows x 512
#define N_SEQ   4096
#define N_CIRC  8192
#define DMODEL  512
#define DEXP    1024
#define NROWS   32768

// ---------------- scratch (static device arrays; no allocations) ----------------
__device__ float  g_xn  [NROWS * DMODEL];
__device__ float  g_u   [NROWS * DEXP];
__device__ float  g_v   [NROWS * DMODEL];
__device__ float  g_ta  [N_CIRC * DMODEL];
__device__ float  g_tb  [N_CIRC * DMODEL];
__device__ float  g_At  [N_CIRC * DMODEL];     // time-domain kernel A (8192 x 512)
__device__ float2 g_Af  [DMODEL * N_CIRC];     // per-channel spectra (bitrev order, pre-scaled 1/8192)
__device__ float  g_conv[NROWS * DMODEL];
__device__ float  g_gate[NROWS * DEXP];

// ---------------- SimpleRMSNorm (+ optional ReLU), 512 cols ----------------
__global__ __launch_bounds__(128) void srms_kernel(const float* __restrict__ in,
                                                   float* __restrict__ out, int relu)
{
    long row = blockIdx.x;
    const float4* rp = reinterpret_cast<const float4*>(in + row * DMODEL);
    float4 v = rp[threadIdx.x];
    float s = v.x * v.x + v.y * v.y + v.z * v.z + v.w * v.w;
    #pragma unroll
    for (int o = 16; o > 0; o >>= 1) s += __shfl_xor_sync(0xffffffffu, s, o);
    __shared__ float ws[4];
    if ((threadIdx.x & 31) == 0) ws[threadIdx.x >> 5] = s;
    __syncthreads();
    float tot = ws[0] + ws[1] + ws[2] + ws[3];
    // x / (||x|| * 512^-0.5 + 1e-8)
    float scale = 1.0f / (sqrtf(tot) * 0.04419417382415922f + 1e-8f);
    float4 o4;
    o4.x = v.x * scale; o4.y = v.y * scale; o4.z = v.z * scale; o4.w = v.w * scale;
    if (relu) {
        o4.x = fmaxf(o4.x, 0.f); o4.y = fmaxf(o4.y, 0.f);
        o4.z = fmaxf(o4.z, 0.f); o4.w = fmaxf(o4.w, 0.f);
    }
    reinterpret_cast<float4*>(out + row * DMODEL)[threadIdx.x] = o4;
}

// ---------------- DPB layer-0: scalar pos -> 512, then srms+relu ----------------
__global__ __launch_bounds__(128) void dpb_in_kernel(const float* __restrict__ Wp,
                                                     const float* __restrict__ bp,
                                                     float* __restrict__ out)
{
    int m = blockIdx.x;
    float p;
    if (m == 0 || m == 4096) p = 0.f;
    else if (m < 4096)       p = (float)m;
    else                     p = (float)(m - 8192);
    float4 w = reinterpret_cast<const float4*>(Wp)[threadIdx.x];
    float4 b = reinterpret_cast<const float4*>(bp)[threadIdx.x];
    float4 v;
    v.x = fmaf(p, w.x, b.x); v.y = fmaf(p, w.y, b.y);
    v.z = fmaf(p, w.z, b.z); v.w = fmaf(p, w.w, b.w);
    float s = v.x * v.x + v.y * v.y + v.z * v.z + v.w * v.w;
    #pragma unroll
    for (int o = 16; o > 0; o >>= 1) s += __shfl_xor_sync(0xffffffffu, s, o);
    __shared__ float ws[4];
    if ((threadIdx.x & 31) == 0) ws[threadIdx.x >> 5] = s;
    __syncthreads();
    float tot = ws[0] + ws[1] + ws[2] + ws[3];
    float scale = 1.0f / (sqrtf(tot) * 0.04419417382415922f + 1e-8f);
    float4 o4;
    o4.x = fmaxf(v.x * scale, 0.f); o4.y = fmaxf(v.y * scale, 0.f);
    o4.z = fmaxf(v.z * scale, 0.f); o4.w = fmaxf(v.w * scale, 0.f);
    reinterpret_cast<float4*>(out + (long)m * DMODEL)[threadIdx.x] = o4;
}

// ---------------- SGEMM: C = epi(A@B + bias)  (128x128x8, 8x8 per thread) ----------------
template<bool SILU, bool GATE, bool RES>
__global__ __launch_bounds__(256) void sgemm_kernel(
    const float* __restrict__ A, const float* __restrict__ B,
    const float* __restrict__ bias, const float* __restrict__ mult,
    const float* __restrict__ res, float* __restrict__ C,
    int M, int N, int K)
{
    __shared__ float As[8][128];
    __shared__ float Bs[8][128];
    int tid = threadIdx.x;
    int aRow = tid >> 1;          // 0..127
    int aCol = (tid & 1) * 4;     // 0 or 4
    int bRow = tid >> 5;          // 0..7
    int bCol = (tid & 31) * 4;
    const float* Ag = A + ((long)blockIdx.y * 128 + aRow) * K + aCol;
    const float* Bg = B + (long)bRow * N + blockIdx.x * 128 + bCol;
    int ty = tid >> 4, tx = tid & 15;

    float acc[8][8];
    #pragma unroll
    for (int i = 0; i < 8; i++)
        #pragma unroll
        for (int j = 0; j < 8; j++) acc[i][j] = 0.f;

    for (int k0 = 0; k0 < K; k0 += 8) {
        float4 av = *reinterpret_cast<const float4*>(Ag + k0);
        As[aCol + 0][aRow] = av.x; As[aCol + 1][aRow] = av.y;
        As[aCol + 2][aRow] = av.z; As[aCol + 3][aRow] = av.w;
        *reinterpret_cast<float4*>(&Bs[bRow][bCol]) =
            *reinterpret_cast<const float4*>(Bg + (long)k0 * N);
        __syncthreads();
        #pragma unroll
        for (int k = 0; k < 8; k++) {
            float am[8], bn[8];
            *reinterpret_cast<float4*>(am)     = *reinterpret_cast<const float4*>(&As[k][ty * 8]);
            *reinterpret_cast<float4*>(am + 4) = *reinterpret_cast<const float4*>(&As[k][ty * 8 + 4]);
            *reinterpret_cast<float4*>(bn)     = *reinterpret_cast<const float4*>(&Bs[k][tx * 8]);
            *reinterpret_cast<float4*>(bn + 4) = *reinterpret_cast<const float4*>(&Bs[k][tx * 8 + 4]);
            #pragma unroll
            for (int i = 0; i < 8; i++)
                #pragma unroll
                for (int j = 0; j < 8; j++)
                    acc[i][j] = fmaf(am[i], bn[j], acc[i][j]);
        }
        __syncthreads();
    }

    #pragma unroll
    for (int i = 0; i < 8; i++) {
        long row = (long)blockIdx.y * 128 + ty * 8 + i;
        #pragma unroll
        for (int j = 0; j < 8; j++) {
            int col = blockIdx.x * 128 + tx * 8 + j;
            float vv = acc[i][j] + bias[col];
            if (SILU) vv = vv / (1.f + __expf(-vv));
            long idx = row * N + col;
            if (GATE) vv *= mult[idx];
            if (RES)  vv += res[idx];
            C[idx] = vv;
        }
    }
}

// ---------------- 8192-pt radix-2 FFT in shared memory ----------------
// Forward: Gentleman-Sande DIF, natural in -> bit-reversed out.
// Inverse: Cooley-Tukey DIT, bit-reversed in -> natural out (conjugate twiddles).
// Elementwise spectral multiply is done in bit-reversed order (consistent for both operands).
__device__ __forceinline__ void fft_fwd(float2* z, int tid)
{
    for (int s = 12; s >= 0; --s) {
        int len = 1 << s;
        for (int idx = tid; idx < 4096; idx += 512) {
            int j = idx & (len - 1);
            int i = ((idx >> s) << (s + 1)) + j;
            float2 u = z[i], w = z[i + len];
            z[i] = make_float2(u.x + w.x, u.y + w.y);
            float dx = u.x - w.x, dy = u.y - w.y;
            float ang = (-PI_F) * (float)j / (float)len;
            float sn, cs; __sincosf(ang, &sn, &cs);
            z[i + len] = make_float2(dx * cs - dy * sn, dx * sn + dy * cs);
        }
        __syncthreads();
    }
}

__device__ __forceinline__ void fft_inv(float2* z, int tid)
{
    for (int s = 0; s <= 12; ++s) {
        int len = 1 << s;
        for (int idx = tid; idx < 4096; idx += 512) {
            int j = idx & (len - 1);
            int i = ((idx >> s) << (s + 1)) + j;
            float ang = PI_F * (float)j / (float)len;
            float sn, cs; __sincosf(ang, &sn, &cs);
            float2 u = z[i], w = z[i + len];
            float txx = w.x * cs - w.y * sn;
            float tyy = w.x * sn + w.y * cs;
            z[i]       = make_float2(u.x + txx, u.y + tyy);
            z[i + len] = make_float2(u.x - txx, u.y - tyy);
        }
        __syncthreads();
    }
}

// Precompute per-channel kernel spectra (bitrev order, scaled by 1/8192)
__global__ __launch_bounds__(512) void af_kernel()
{
    extern __shared__ float2 z[];
    int c = blockIdx.x, tid = threadIdx.x;
    for (int m = tid; m < N_CIRC; m += 512)
        z[m] = make_float2(g_At[(long)m * DMODEL + c], 0.f);
    __syncthreads();
    fft_fwd(z, tid);
    const float inv = 1.0f / 8192.0f;
    for (int k = tid; k < N_CIRC; k += 512) {
        float2 v = z[k];
        g_Af[(long)c * N_CIRC + k] = make_float2(v.x * inv, v.y * inv);
    }
}

// Per-(batch, channel) circular convolution: out = irfft(fft(v_pad) * Af)[:4096]
__global__ __launch_bounds__(512) void conv_kernel()
{
    extern __shared__ float2 z[];
    int blk = blockIdx.x;
    int b = blk >> 9, c = blk & 511;
    int tid = threadIdx.x;
    const float* vp = g_v + ((long)b * N_SEQ) * DMODEL + c;
    for (int j = tid; j < N_SEQ; j += 512)
        z[j] = make_float2(vp[(long)j * DMODEL], 0.f);
    for (int j = N_SEQ + tid; j < N_CIRC; j += 512)
        z[j] = make_float2(0.f, 0.f);
    __syncthreads();
    fft_fwd(z, tid);
    const float2* af = g_Af + (long)c * N_CIRC;
    for (int k = tid; k < N_CIRC; k += 512) {
        float2 a = af[k], v = z[k];
        z[k] = make_float2(v.x * a.x - v.y * a.y, v.x * a.y + v.y * a.x);
    }
    __syncthreads();
    fft_inv(z, tid);
    float* op = g_conv + ((long)b * N_SEQ) * DMODEL + c;
    for (int i = tid; i < N_SEQ; i += 512)
        op[(long)i * DMODEL] = z[i].x;
}

// ---------------- host launch ----------------
static float* sym_f(const void* s) { void* p = nullptr; cudaGetSymbolAddress(&p, s); return (float*)p; }

extern "C" void kernel_launch(void* const* d_in, const int* in_sizes, int n_in,
                              void* d_out, int out_size)
{
    const float* x   = (const float*)d_in[0];
    const float* Wu  = (const float*)d_in[1];
    const float* bu  = (const float*)d_in[2];
    const float* Wv  = (const float*)d_in[3];
    const float* bv  = (const float*)d_in[4];
    const float* Wo1 = (const float*)d_in[5];
    const float* bo1 = (const float*)d_in[6];
    const float* Wo2 = (const float*)d_in[7];
    const float* bo2 = (const float*)d_in[8];
    const float* dWp = (const float*)d_in[9];
    const float* dbp = (const float*)d_in[10];
    const float* dW1 = (const float*)d_in[11];
    const float* db1 = (const float*)d_in[12];
    const float* dW2 = (const float*)d_in[13];
    const float* db2 = (const float*)d_in[14];
    const float* dW3 = (const float*)d_in[15];
    const float* db3 = (const float*)d_in[16];
    float* out = (float*)d_out;

    cudaFuncSetAttribute(af_kernel,   cudaFuncAttributeMaxDynamicSharedMemorySize, 65536);
    cudaFuncSetAttribute(conv_kernel, cudaFuncAttributeMaxDynamicSharedMemorySize, 65536);

    float* p_xn   = sym_f(g_xn);
    float* p_u    = sym_f(g_u);
    float* p_v    = sym_f(g_v);
    float* p_ta   = sym_f(g_ta);
    float* p_tb   = sym_f(g_tb);
    float* p_At   = sym_f(g_At);
    float* p_conv = sym_f(g_conv);
    float* p_gate = sym_f(g_gate);

    // 1) pre-norm
    srms_kernel<<<NROWS, 128>>>(x, p_xn, 0);
    // 2) u = silu(xn @ Wu + bu), v = silu(xn @ Wv + bv)
    sgemm_kernel<true,  false, false><<<dim3(8, 256), 256>>>(p_xn, Wu, bu, nullptr, nullptr, p_u, NROWS, DEXP,   DMODEL);
    sgemm_kernel<true,  false, false><<<dim3(4, 256), 256>>>(p_xn, Wv, bv, nullptr, nullptr, p_v, NROWS, DMODEL, DMODEL);
    // 3) DPB MLP over all 8192 circulant positions
    dpb_in_kernel<<<N_CIRC, 128>>>(dWp, dbp, p_ta);
    sgemm_kernel<false, false, false><<<dim3(4, 64), 256>>>(p_ta, dW1, db1, nullptr, nullptr, p_tb, N_CIRC, DMODEL, DMODEL);
    srms_kernel<<<N_CIRC, 128>>>(p_tb, p_ta, 1);
    sgemm_kernel<false, false, false><<<dim3(4, 64), 256>>>(p_ta, dW2, db2, nullptr, nullptr, p_tb, N_CIRC, DMODEL, DMODEL);
    srms_kernel<<<N_CIRC, 128>>>(p_tb, p_ta, 1);
    sgemm_kernel<false, false, false><<<dim3(4, 64), 256>>>(p_ta, dW3, db3, nullptr, nullptr, p_At, N_CIRC, DMODEL, DMODEL);
    // 4) kernel spectra + spectral convolution
    af_kernel<<<DMODEL, 512, 65536>>>();
    conv_kernel<<<NROWS / 8, 512, 65536>>>();   // 4096 blocks = batch(8) x channels(512)
    // 5) gate + output projection + residual
    sgemm_kernel<false, true,  false><<<dim3(8, 256), 256>>>(p_conv, Wo1, bo1, p_u, nullptr, p_gate, NROWS, DEXP,   DMODEL);
    sgemm_kernel<false, false, true ><<<dim3(4, 256), 256>>>(p_gate, Wo2, bo2, nullptr, x, out, NROWS, DMODEL, DEXP);
}